// round 4
// baseline (speedup 1.0000x reference)
#include <cuda_runtime.h>
#include <math.h>

#define NN 100000
#define EE 1600000
#define OUTD 64
#define IND 128
#define NBLK ((NN + 255) / 256)   // 391 scan blocks

// ---- scratch (static __device__ arrays; no allocation allowed) ----
static __device__ float g_Wh[(size_t)NN * OUTD];        // 25.6 MB
static __device__ float g_asrc[NN * 4];
static __device__ float g_adst[NN * 4];
static __device__ int   g_count[NN];
static __device__ int   g_rowstart[NN];
static __device__ int   g_cursor[NN];
static __device__ int   g_bsum[NBLK];
static __device__ int   g_bsumx[NBLK];
static __device__ int   g_csr_src[EE];                  // 6.4 MB
static __device__ float g_csr_e[(size_t)EE * 4];        // 25.6 MB (logits)
static __device__ unsigned g_maxbits;

__device__ __forceinline__ unsigned enc_f(float f) {
    unsigned u = __float_as_uint(f);
    return (u & 0x80000000u) ? ~u : (u | 0x80000000u);
}
__device__ __forceinline__ float dec_f(unsigned u) {
    int i = (u & 0x80000000u) ? (int)(u & 0x7fffffffu) : (int)~u;
    return __int_as_float(i);
}
__device__ __forceinline__ float dot4(float4 a, float4 b) {
    return a.x * b.x + a.y * b.y + a.z * b.z + a.w * b.w;
}

// ---- K0: zero counts ----
__global__ void k_init() {
    int i = blockIdx.x * blockDim.x + threadIdx.x;
    if (i < NN) g_count[i] = 0;
    if (i == 0) g_maxbits = 0u;
}

// ---- K0b: degree histogram ----
__global__ void __launch_bounds__(256) k_count(const int* __restrict__ ei) {
    int i = blockIdx.x * 256 + threadIdx.x;
    if (i < EE) atomicAdd(&g_count[__ldg(ei + EE + i)], 1);
}

// ---- K1: register-blocked GEMM Wh = x @ Wn^T, fused a_src/a_dst ----
__global__ void __launch_bounds__(256) k_node(
    const float* __restrict__ x, const float* __restrict__ Wn,
    const float* __restrict__ att_s, const float* __restrict__ att_d) {
    int n0 = blockIdx.x * 64;
    int t = threadIdx.x;
    int tx = t & 15, ty = t >> 4;

    int node[4];
    const float4* xp[4];
#pragma unroll
    for (int i = 0; i < 4; i++) {
        node[i] = n0 + ty * 4 + i;
        int nc = (node[i] < NN) ? node[i] : (NN - 1);
        xp[i] = (const float4*)x + (size_t)nc * 32;
    }
    const float4* wp0 = (const float4*)Wn + (size_t)(tx) * 32;
    const float4* wp1 = (const float4*)Wn + (size_t)(tx + 16) * 32;
    const float4* wp2 = (const float4*)Wn + (size_t)(tx + 32) * 32;
    const float4* wp3 = (const float4*)Wn + (size_t)(tx + 48) * 32;

    float acc[4][4];
#pragma unroll
    for (int i = 0; i < 4; i++)
#pragma unroll
        for (int j = 0; j < 4; j++) acc[i][j] = 0.f;

#pragma unroll 8
    for (int kk = 0; kk < 32; kk++) {
        float4 b0 = __ldg(wp0 + kk);
        float4 b1 = __ldg(wp1 + kk);
        float4 b2 = __ldg(wp2 + kk);
        float4 b3 = __ldg(wp3 + kk);
#pragma unroll
        for (int i = 0; i < 4; i++) {
            float4 a = __ldg(xp[i] + kk);
            acc[i][0] += dot4(a, b0);
            acc[i][1] += dot4(a, b1);
            acc[i][2] += dot4(a, b2);
            acc[i][3] += dot4(a, b3);
        }
    }

    float ats[4], atd[4];
#pragma unroll
    for (int j = 0; j < 4; j++) {
        ats[j] = __ldg(att_s + 16 * j + tx);
        atd[j] = __ldg(att_d + 16 * j + tx);
    }
#pragma unroll
    for (int i = 0; i < 4; i++) {
        float4 ps, pd;
        float* psp = (float*)&ps;
        float* pdp = (float*)&pd;
#pragma unroll
        for (int j = 0; j < 4; j++) {
            psp[j] = acc[i][j] * ats[j];
            pdp[j] = acc[i][j] * atd[j];
        }
#pragma unroll
        for (int o = 8; o >= 1; o >>= 1) {
#pragma unroll
            for (int j = 0; j < 4; j++) {
                psp[j] += __shfl_xor_sync(0xffffffffu, psp[j], o);
                pdp[j] += __shfl_xor_sync(0xffffffffu, pdp[j], o);
            }
        }
        if (tx == 0 && node[i] < NN) {
            *(float4*)(g_asrc + (size_t)node[i] * 4) = ps;
            *(float4*)(g_adst + (size_t)node[i] * 4) = pd;
        }
    }

#pragma unroll
    for (int i = 0; i < 4; i++) {
        if (node[i] < NN) {
            float* o = g_Wh + (size_t)node[i] * OUTD + tx;
#pragma unroll
            for (int j = 0; j < 4; j++) o[16 * j] = acc[i][j];
        }
    }
}

// ---- scan pass 1 ----
__global__ void __launch_bounds__(256) k_scan_bsum() {
    __shared__ int ws[8];
    int i = blockIdx.x * 256 + threadIdx.x;
    int c = (i < NN) ? g_count[i] : 0;
#pragma unroll
    for (int o = 16; o >= 1; o >>= 1) c += __shfl_xor_sync(0xffffffffu, c, o);
    if ((threadIdx.x & 31) == 0) ws[threadIdx.x >> 5] = c;
    __syncthreads();
    if (threadIdx.x < 8) {
        c = ws[threadIdx.x];
#pragma unroll
        for (int o = 4; o >= 1; o >>= 1) c += __shfl_xor_sync(0xffu, c, o);
        if (threadIdx.x == 0) g_bsum[blockIdx.x] = c;
    }
}

// ---- scan pass 2 ----
__global__ void __launch_bounds__(512) k_scan_top() {
    __shared__ int sh[512];
    int t = threadIdx.x;
    int v = (t < NBLK) ? g_bsum[t] : 0;
    sh[t] = v;
    __syncthreads();
#pragma unroll
    for (int o = 1; o < 512; o <<= 1) {
        int add = (t >= o) ? sh[t - o] : 0;
        __syncthreads();
        sh[t] += add;
        __syncthreads();
    }
    if (t < NBLK) g_bsumx[t] = sh[t] - v;
}

// ---- scan pass 3 ----
__global__ void __launch_bounds__(256) k_scan_fin() {
    __shared__ int sh[256];
    int t = threadIdx.x;
    int i = blockIdx.x * 256 + t;
    int c = (i < NN) ? g_count[i] : 0;
    sh[t] = c;
    __syncthreads();
#pragma unroll
    for (int o = 1; o < 256; o <<= 1) {
        int add = (t >= o) ? sh[t - o] : 0;
        __syncthreads();
        sh[t] += add;
        __syncthreads();
    }
    if (i < NN) {
        int start = sh[t] - c + g_bsumx[blockIdx.x];
        g_rowstart[i] = start;
        g_cursor[i] = start;
    }
}

// ---- K2: logits -> CSR slots directly, global max ----
__global__ void __launch_bounds__(256) k_edge_e(
    const int* __restrict__ ei, const float* __restrict__ ea,
    const float* __restrict__ We) {
    __shared__ float we[64];
    __shared__ float wmax[8];
    int t = threadIdx.x;
    if (t < 64) we[t] = We[t];
    __syncthreads();
    int i = blockIdx.x * 256 + t;
    float m = -1e30f;
    if (i < EE) {
        int s = ei[i];
        int d = ei[EE + i];
        float eav[16];
        const float4* er = (const float4*)(ea + (size_t)i * 16);
#pragma unroll
        for (int j = 0; j < 4; j++) ((float4*)eav)[j] = __ldg(er + j);
        float4 as = *(const float4*)(g_asrc + (size_t)s * 4);
        float4 ad = *(const float4*)(g_adst + (size_t)d * 4);
        float base[4] = {as.x + ad.x, as.y + ad.y, as.z + ad.z, as.w + ad.w};
        float4 ev;
        float* evp = (float*)&ev;
#pragma unroll
        for (int h = 0; h < 4; h++) {
            float dot = 0.f;
            const float* w = we + h * 16;
#pragma unroll
            for (int k = 0; k < 16; k++) dot += eav[k] * w[k];
            float v = base[h] + dot;
            v = (v > 0.f) ? v : 0.2f * v;
            evp[h] = v;
            m = fmaxf(m, v);
        }
        int pos = atomicAdd(&g_cursor[d], 1);
        g_csr_src[pos] = s;
        *(float4*)(g_csr_e + (size_t)pos * 4) = ev;
    }
#pragma unroll
    for (int o = 16; o >= 1; o >>= 1) m = fmaxf(m, __shfl_xor_sync(0xffffffffu, m, o));
    if ((t & 31) == 0) wmax[t >> 5] = m;
    __syncthreads();
    if (t < 8) {
        m = wmax[t];
#pragma unroll
        for (int o = 4; o >= 1; o >>= 1) m = fmaxf(m, __shfl_xor_sync(0xffu, m, o));
        if (t == 0) atomicMax(&g_maxbits, enc_f(m));
    }
}

// ---- K3: warp-per-node aggregate; exp fused here; bias+ELU fused ----
__global__ void __launch_bounds__(256) k_agg(float* __restrict__ out,
                                             const float* __restrict__ bias) {
    int n = (blockIdx.x * 256 + threadIdx.x) >> 5;
    int lane = threadIdx.x & 31;
    if (n >= NN) return;
    int cnt = __ldg(g_count + n);
    int start = __ldg(g_rowstart + n);
    float mx = dec_f(g_maxbits);
    int h = lane >> 3;                 // cols 2*lane, 2*lane+1 -> head = lane/8
    float acc0 = 0.f, acc1 = 0.f;
    float dp0 = 0.f, dp1 = 0.f, dp2 = 0.f, dp3 = 0.f;

    for (int j0 = 0; j0 < cnt; j0 += 32) {
        int m = min(32, cnt - j0);
        int src = 0;
        float ex0 = 0.f, ex1 = 0.f, ex2 = 0.f, ex3 = 0.f;
        if (lane < m) {
            int idx = start + j0 + lane;
            src = __ldg(g_csr_src + idx);
            float4 e = *(const float4*)(g_csr_e + (size_t)idx * 4);
            ex0 = __expf(e.x - mx);
            ex1 = __expf(e.y - mx);
            ex2 = __expf(e.z - mx);
            ex3 = __expf(e.w - mx);
            dp0 += ex0; dp1 += ex1; dp2 += ex2; dp3 += ex3;
        }
        for (int j = 0; j < m; j++) {
            int s = __shfl_sync(0xffffffffu, src, j);
            float a0 = __shfl_sync(0xffffffffu, ex0, j);
            float a1 = __shfl_sync(0xffffffffu, ex1, j);
            float a2 = __shfl_sync(0xffffffffu, ex2, j);
            float a3 = __shfl_sync(0xffffffffu, ex3, j);
            float a = (h == 0) ? a0 : (h == 1) ? a1 : (h == 2) ? a2 : a3;
            float2 w = *(const float2*)(g_Wh + (size_t)s * OUTD + lane * 2);
            acc0 += a * w.x;
            acc1 += a * w.y;
        }
    }
    // warp-reduce den partials
#pragma unroll
    for (int o = 16; o >= 1; o >>= 1) {
        dp0 += __shfl_xor_sync(0xffffffffu, dp0, o);
        dp1 += __shfl_xor_sync(0xffffffffu, dp1, o);
        dp2 += __shfl_xor_sync(0xffffffffu, dp2, o);
        dp3 += __shfl_xor_sync(0xffffffffu, dp3, o);
    }
    float den = (h == 0) ? dp0 : (h == 1) ? dp1 : (h == 2) ? dp2 : dp3;
    float inv = 1.f / (den + 1e-9f);
    int c0 = lane * 2;
    float v0 = acc0 * inv + __ldg(bias + c0);
    float v1 = acc1 * inv + __ldg(bias + c0 + 1);
    float2 r;
    r.x = (v0 > 0.f) ? v0 : expm1f(v0);
    r.y = (v1 > 0.f) ? v1 : expm1f(v1);
    *(float2*)(out + (size_t)n * OUTD + c0) = r;
}

extern "C" void kernel_launch(void* const* d_in, const int* in_sizes, int n_in,
                              void* d_out, int out_size) {
    const float* x     = (const float*)d_in[0];
    const int*   ei    = (const int*)d_in[1];
    const float* ea    = (const float*)d_in[2];
    const float* Wn    = (const float*)d_in[3];
    const float* We    = (const float*)d_in[4];
    const float* att_s = (const float*)d_in[5];
    const float* att_d = (const float*)d_in[6];
    const float* bias  = (const float*)d_in[7];
    float* out = (float*)d_out;

    int ebl = (EE + 255) / 256;
    k_init<<<NBLK, 256>>>();
    k_count<<<ebl, 256>>>(ei);
    k_node<<<(NN + 63) / 64, 256>>>(x, Wn, att_s, att_d);
    k_scan_bsum<<<NBLK, 256>>>();
    k_scan_top<<<1, 512>>>();
    k_scan_fin<<<NBLK, 256>>>();
    k_edge_e<<<ebl, 256>>>(ei, ea, We);
    k_agg<<<(NN * 32 + 255) / 256, 256>>>(out, bias);
}

// round 5
// speedup vs baseline: 1.1093x; 1.1093x over previous
#include <cuda_runtime.h>
#include <math.h>

#define NN 100000
#define EE 1600000
#define OUTD 64
#define IND 128
#define NBLK ((NN + 255) / 256)   // 391 scan blocks

// ---- scratch (static __device__ arrays; no allocation allowed) ----
static __device__ float g_Wh[(size_t)NN * OUTD];        // 25.6 MB
static __device__ float g_asrc[NN * 4];
static __device__ float g_adst[NN * 4];
static __device__ float g_e[(size_t)EE * 4];            // 25.6 MB logits
static __device__ int   g_count[NN];
static __device__ int   g_rowstart[NN];
static __device__ int   g_cursor[NN];
static __device__ int   g_bsum[NBLK];
static __device__ int   g_bsumx[NBLK];
static __device__ int   g_csr_src[EE];                  // 6.4 MB
static __device__ float g_csr_ex[(size_t)EE * 4];       // 25.6 MB
static __device__ unsigned g_maxbits;

__device__ __forceinline__ unsigned enc_f(float f) {
    unsigned u = __float_as_uint(f);
    return (u & 0x80000000u) ? ~u : (u | 0x80000000u);
}
__device__ __forceinline__ float dec_f(unsigned u) {
    int i = (u & 0x80000000u) ? (int)(u & 0x7fffffffu) : (int)~u;
    return __int_as_float(i);
}
__device__ __forceinline__ float dot4(float4 a, float4 b) {
    return a.x * b.x + a.y * b.y + a.z * b.z + a.w * b.w;
}

// ---- K0a: zero counts ----
__global__ void k_init_cnt() {
    int i = blockIdx.x * blockDim.x + threadIdx.x;
    if (i < NN) g_count[i] = 0;
}
// ---- K0b: reset max ----
__global__ void k_init_max() { g_maxbits = 0u; }

// ---- K1: register-blocked GEMM Wh = x @ Wn^T, fused a_src/a_dst ----
__global__ void __launch_bounds__(256) k_node(
    const float* __restrict__ x, const float* __restrict__ Wn,
    const float* __restrict__ att_s, const float* __restrict__ att_d) {
    int n0 = blockIdx.x * 64;
    int t = threadIdx.x;
    int tx = t & 15, ty = t >> 4;

    int node[4];
    const float4* xp[4];
#pragma unroll
    for (int i = 0; i < 4; i++) {
        node[i] = n0 + ty * 4 + i;
        int nc = (node[i] < NN) ? node[i] : (NN - 1);
        xp[i] = (const float4*)x + (size_t)nc * 32;
    }
    const float4* wp0 = (const float4*)Wn + (size_t)(tx) * 32;
    const float4* wp1 = (const float4*)Wn + (size_t)(tx + 16) * 32;
    const float4* wp2 = (const float4*)Wn + (size_t)(tx + 32) * 32;
    const float4* wp3 = (const float4*)Wn + (size_t)(tx + 48) * 32;

    float acc[4][4];
#pragma unroll
    for (int i = 0; i < 4; i++)
#pragma unroll
        for (int j = 0; j < 4; j++) acc[i][j] = 0.f;

#pragma unroll 8
    for (int kk = 0; kk < 32; kk++) {
        float4 b0 = __ldg(wp0 + kk);
        float4 b1 = __ldg(wp1 + kk);
        float4 b2 = __ldg(wp2 + kk);
        float4 b3 = __ldg(wp3 + kk);
#pragma unroll
        for (int i = 0; i < 4; i++) {
            float4 a = __ldg(xp[i] + kk);
            acc[i][0] += dot4(a, b0);
            acc[i][1] += dot4(a, b1);
            acc[i][2] += dot4(a, b2);
            acc[i][3] += dot4(a, b3);
        }
    }

    float ats[4], atd[4];
#pragma unroll
    for (int j = 0; j < 4; j++) {
        ats[j] = __ldg(att_s + 16 * j + tx);
        atd[j] = __ldg(att_d + 16 * j + tx);
    }
#pragma unroll
    for (int i = 0; i < 4; i++) {
        float4 ps, pd;
        float* psp = (float*)&ps;
        float* pdp = (float*)&pd;
#pragma unroll
        for (int j = 0; j < 4; j++) {
            psp[j] = acc[i][j] * ats[j];
            pdp[j] = acc[i][j] * atd[j];
        }
#pragma unroll
        for (int o = 8; o >= 1; o >>= 1) {
#pragma unroll
            for (int j = 0; j < 4; j++) {
                psp[j] += __shfl_xor_sync(0xffffffffu, psp[j], o);
                pdp[j] += __shfl_xor_sync(0xffffffffu, pdp[j], o);
            }
        }
        if (tx == 0 && node[i] < NN) {
            *(float4*)(g_asrc + (size_t)node[i] * 4) = ps;
            *(float4*)(g_adst + (size_t)node[i] * 4) = pd;
        }
    }

#pragma unroll
    for (int i = 0; i < 4; i++) {
        if (node[i] < NN) {
            float* o = g_Wh + (size_t)node[i] * OUTD + tx;
#pragma unroll
            for (int j = 0; j < 4; j++) o[16 * j] = acc[i][j];
        }
    }
}

// ---- K2: e = leaky_relu(...), global max, degree histogram ----
__global__ void __launch_bounds__(256) k_edge_e(
    const int* __restrict__ ei, const float* __restrict__ ea,
    const float* __restrict__ We) {
    __shared__ float we[64];
    __shared__ float wmax[8];
    int t = threadIdx.x;
    if (t < 64) we[t] = We[t];
    __syncthreads();
    int i = blockIdx.x * 256 + t;
    float m = -1e30f;
    if (i < EE) {
        int s = ei[i];
        int d = ei[EE + i];
        float eav[16];
        const float4* er = (const float4*)(ea + (size_t)i * 16);
#pragma unroll
        for (int j = 0; j < 4; j++) ((float4*)eav)[j] = __ldg(er + j);
        float4 as = *(const float4*)(g_asrc + (size_t)s * 4);
        float4 ad = *(const float4*)(g_adst + (size_t)d * 4);
        float base[4] = {as.x + ad.x, as.y + ad.y, as.z + ad.z, as.w + ad.w};
        float4 ev;
        float* evp = (float*)&ev;
#pragma unroll
        for (int h = 0; h < 4; h++) {
            float dot = 0.f;
            const float* w = we + h * 16;
#pragma unroll
            for (int k = 0; k < 16; k++) dot += eav[k] * w[k];
            float v = base[h] + dot;
            v = (v > 0.f) ? v : 0.2f * v;
            evp[h] = v;
            m = fmaxf(m, v);
        }
        *(float4*)(g_e + (size_t)i * 4) = ev;
        atomicAdd(&g_count[d], 1);
    }
#pragma unroll
    for (int o = 16; o >= 1; o >>= 1) m = fmaxf(m, __shfl_xor_sync(0xffffffffu, m, o));
    if ((t & 31) == 0) wmax[t >> 5] = m;
    __syncthreads();
    if (t < 8) {
        m = wmax[t];
#pragma unroll
        for (int o = 4; o >= 1; o >>= 1) m = fmaxf(m, __shfl_xor_sync(0xffu, m, o));
        if (t == 0) atomicMax(&g_maxbits, enc_f(m));
    }
}

// ---- scan pass 1 ----
__global__ void __launch_bounds__(256) k_scan_bsum() {
    __shared__ int ws[8];
    int i = blockIdx.x * 256 + threadIdx.x;
    int c = (i < NN) ? g_count[i] : 0;
#pragma unroll
    for (int o = 16; o >= 1; o >>= 1) c += __shfl_xor_sync(0xffffffffu, c, o);
    if ((threadIdx.x & 31) == 0) ws[threadIdx.x >> 5] = c;
    __syncthreads();
    if (threadIdx.x < 8) {
        c = ws[threadIdx.x];
#pragma unroll
        for (int o = 4; o >= 1; o >>= 1) c += __shfl_xor_sync(0xffu, c, o);
        if (threadIdx.x == 0) g_bsum[blockIdx.x] = c;
    }
}

// ---- scan pass 2 ----
__global__ void __launch_bounds__(512) k_scan_top() {
    __shared__ int sh[512];
    int t = threadIdx.x;
    int v = (t < NBLK) ? g_bsum[t] : 0;
    sh[t] = v;
    __syncthreads();
#pragma unroll
    for (int o = 1; o < 512; o <<= 1) {
        int add = (t >= o) ? sh[t - o] : 0;
        __syncthreads();
        sh[t] += add;
        __syncthreads();
    }
    if (t < NBLK) g_bsumx[t] = sh[t] - v;
}

// ---- scan pass 3 ----
__global__ void __launch_bounds__(256) k_scan_fin() {
    __shared__ int sh[256];
    int t = threadIdx.x;
    int i = blockIdx.x * 256 + t;
    int c = (i < NN) ? g_count[i] : 0;
    sh[t] = c;
    __syncthreads();
#pragma unroll
    for (int o = 1; o < 256; o <<= 1) {
        int add = (t >= o) ? sh[t - o] : 0;
        __syncthreads();
        sh[t] += add;
        __syncthreads();
    }
    if (i < NN) {
        int start = sh[t] - c + g_bsumx[blockIdx.x];
        g_rowstart[i] = start;
        g_cursor[i] = start;
    }
}

// ---- K3: exp + CSR bucket-scatter of (src, ex4) ----
__global__ void __launch_bounds__(256) k_csr(const int* __restrict__ ei) {
    int i = blockIdx.x * 256 + threadIdx.x;
    if (i >= EE) return;
    float mx = dec_f(g_maxbits);
    int s = __ldg(ei + i);
    int d = __ldg(ei + EE + i);
    float4 e = *(const float4*)(g_e + (size_t)i * 4);
    float4 ex = make_float4(expf(e.x - mx), expf(e.y - mx),
                            expf(e.z - mx), expf(e.w - mx));
    int pos = atomicAdd(&g_cursor[d], 1);
    g_csr_src[pos] = s;
    *(float4*)(g_csr_ex + (size_t)pos * 4) = ex;
}

// ---- K4: warp-per-node aggregate, LDS-staged, 4x-unrolled gathers ----
__global__ void __launch_bounds__(256) k_agg(float* __restrict__ out,
                                             const float* __restrict__ bias) {
    __shared__ int   sh_src[8][32];
    __shared__ float sh_ex[8][128];
    int w = threadIdx.x >> 5;
    int lane = threadIdx.x & 31;
    int n = blockIdx.x * 8 + w;
    if (n >= NN) return;
    int cnt = __ldg(g_count + n);
    int start = __ldg(g_rowstart + n);
    int h = lane >> 3;                 // cols 2*lane, 2*lane+1 -> head = lane/8
    float acc0 = 0.f, acc1 = 0.f;
    float dp0 = 0.f, dp1 = 0.f, dp2 = 0.f, dp3 = 0.f;

    for (int j0 = 0; j0 < cnt; j0 += 32) {
        int m = min(32, cnt - j0);
        if (lane < m) {
            int idx = start + j0 + lane;
            int s = __ldg(g_csr_src + idx);
            float4 ex = *(const float4*)(g_csr_ex + (size_t)idx * 4);
            sh_src[w][lane] = s;
            *(float4*)&sh_ex[w][lane * 4] = ex;
            dp0 += ex.x; dp1 += ex.y; dp2 += ex.z; dp3 += ex.w;
        }
        __syncwarp();
        int j = 0;
        for (; j + 4 <= m; j += 4) {
            int s0 = sh_src[w][j + 0], s1 = sh_src[w][j + 1];
            int s2 = sh_src[w][j + 2], s3 = sh_src[w][j + 3];
            float a0 = sh_ex[w][(j + 0) * 4 + h];
            float a1 = sh_ex[w][(j + 1) * 4 + h];
            float a2 = sh_ex[w][(j + 2) * 4 + h];
            float a3 = sh_ex[w][(j + 3) * 4 + h];
            float2 w0 = *(const float2*)(g_Wh + (size_t)s0 * OUTD + lane * 2);
            float2 w1 = *(const float2*)(g_Wh + (size_t)s1 * OUTD + lane * 2);
            float2 w2 = *(const float2*)(g_Wh + (size_t)s2 * OUTD + lane * 2);
            float2 w3 = *(const float2*)(g_Wh + (size_t)s3 * OUTD + lane * 2);
            acc0 += a0 * w0.x + a1 * w1.x + a2 * w2.x + a3 * w3.x;
            acc1 += a0 * w0.y + a1 * w1.y + a2 * w2.y + a3 * w3.y;
        }
        for (; j < m; j++) {
            int s = sh_src[w][j];
            float a = sh_ex[w][j * 4 + h];
            float2 wv = *(const float2*)(g_Wh + (size_t)s * OUTD + lane * 2);
            acc0 += a * wv.x;
            acc1 += a * wv.y;
        }
        __syncwarp();
    }
#pragma unroll
    for (int o = 16; o >= 1; o >>= 1) {
        dp0 += __shfl_xor_sync(0xffffffffu, dp0, o);
        dp1 += __shfl_xor_sync(0xffffffffu, dp1, o);
        dp2 += __shfl_xor_sync(0xffffffffu, dp2, o);
        dp3 += __shfl_xor_sync(0xffffffffu, dp3, o);
    }
    float den = (h == 0) ? dp0 : (h == 1) ? dp1 : (h == 2) ? dp2 : dp3;
    float inv = 1.f / (den + 1e-9f);
    int c0 = lane * 2;
    float v0 = acc0 * inv + __ldg(bias + c0);
    float v1 = acc1 * inv + __ldg(bias + c0 + 1);
    float2 r;
    r.x = (v0 > 0.f) ? v0 : expm1f(v0);
    r.y = (v1 > 0.f) ? v1 : expm1f(v1);
    *(float2*)(out + (size_t)n * OUTD + c0) = r;
}

extern "C" void kernel_launch(void* const* d_in, const int* in_sizes, int n_in,
                              void* d_out, int out_size) {
    const float* x     = (const float*)d_in[0];
    const int*   ei    = (const int*)d_in[1];
    const float* ea    = (const float*)d_in[2];
    const float* Wn    = (const float*)d_in[3];
    const float* We    = (const float*)d_in[4];
    const float* att_s = (const float*)d_in[5];
    const float* att_d = (const float*)d_in[6];
    const float* bias  = (const float*)d_in[7];
    float* out = (float*)d_out;

    int ebl = (EE + 255) / 256;
    k_init_cnt<<<NBLK, 256>>>();                       // 1
    k_init_max<<<1, 1>>>();                            // 2
    k_node<<<(NN + 63) / 64, 256>>>(x, Wn, att_s, att_d); // 3
    k_edge_e<<<ebl, 256>>>(ei, ea, We);                // 4  <- ncu lands here
    k_scan_bsum<<<NBLK, 256>>>();                      // 5
    k_scan_top<<<1, 512>>>();                          // 6
    k_scan_fin<<<NBLK, 256>>>();                       // 7
    k_csr<<<ebl, 256>>>(ei);                           // 8
    k_agg<<<(NN + 7) / 8, 256>>>(out, bias);           // 9
}